// round 1
// baseline (speedup 1.0000x reference)
#include <cuda_runtime.h>
#include <cstdint>

#define T_TOKENS 16384
#define DDIM     4096
#define NEXP     64
#define MT       64      // tokens per CTA
#define KT       16      // K chunk
#define NTHREADS 128
#define LSTRIDE  68      // padded logits row stride (floats), 68*4=272 = 16B multiple

// ---- packed f32x2 helpers (sm_100+ PTX) ----
__device__ __forceinline__ unsigned long long pack2(float lo, float hi) {
    unsigned long long r;
    asm("mov.b64 %0, {%1, %2};" : "=l"(r) : "f"(lo), "f"(hi));
    return r;
}
__device__ __forceinline__ void unpack2(unsigned long long v, float& lo, float& hi) {
    asm("mov.b64 {%0, %1}, %2;" : "=f"(lo), "=f"(hi) : "l"(v));
}
__device__ __forceinline__ void fma2(unsigned long long& acc,
                                     unsigned long long a, unsigned long long b) {
    asm("fma.rn.f32x2 %0, %1, %2, %0;" : "+l"(acc) : "l"(a), "l"(b));
}

// smem: double-buffered h tile (2*KT*MT = 2048 f) + W tile (2*KT*NEXP = 2048 f),
// reused as logits scratch (MT*LSTRIDE = 4352 f) in the epilogue.
#define SMEM_FLOATS 4352
#define WS_OFF      2048

__global__ __launch_bounds__(NTHREADS)
void gate_kernel(const float* __restrict__ h,
                 const float* __restrict__ W,
                 float* __restrict__ out)
{
    __shared__ __align__(16) float sbuf[SMEM_FLOATS];

    const int tid = threadIdx.x;
    const int tx  = tid & 15;   // token group: tokens tx*4 .. tx*4+3
    const int ty  = tid >> 4;   // expert group: experts ty*8 .. ty*8+7

    const float* hblk = h + (size_t)blockIdx.x * MT * DDIM;

    // global staging registers (2 float4 for h tile, 2 for W tile per chunk)
    float4 ha0, ha1, wa0, wa1;
    const int q0 = tid, q1 = tid + NTHREADS;
    const int r0 = q0 >> 2, c0 = (q0 & 3) * 4;   // row (token/expert), k sub-offset
    const int r1 = q1 >> 2, c1 = (q1 & 3) * 4;

    unsigned long long acc[4][4];
#pragma unroll
    for (int j = 0; j < 4; j++)
#pragma unroll
        for (int p = 0; p < 4; p++) acc[j][p] = 0ULL;

    // ---- prologue: load + store chunk 0 ----
    {
        const int k0 = 0;
        ha0 = *(const float4*)(hblk + (size_t)r0 * DDIM + k0 + c0);
        ha1 = *(const float4*)(hblk + (size_t)r1 * DDIM + k0 + c1);
        wa0 = *(const float4*)(W    + (size_t)r0 * DDIM + k0 + c0);
        wa1 = *(const float4*)(W    + (size_t)r1 * DDIM + k0 + c1);
        float* hb = sbuf;            // buffer 0
        float* wb = sbuf + WS_OFF;
        hb[(c0 + 0) * MT + r0] = ha0.x; hb[(c0 + 1) * MT + r0] = ha0.y;
        hb[(c0 + 2) * MT + r0] = ha0.z; hb[(c0 + 3) * MT + r0] = ha0.w;
        hb[(c1 + 0) * MT + r1] = ha1.x; hb[(c1 + 1) * MT + r1] = ha1.y;
        hb[(c1 + 2) * MT + r1] = ha1.z; hb[(c1 + 3) * MT + r1] = ha1.w;
        wb[(c0 + 0) * NEXP + r0] = wa0.x; wb[(c0 + 1) * NEXP + r0] = wa0.y;
        wb[(c0 + 2) * NEXP + r0] = wa0.z; wb[(c0 + 3) * NEXP + r0] = wa0.w;
        wb[(c1 + 0) * NEXP + r1] = wa1.x; wb[(c1 + 1) * NEXP + r1] = wa1.y;
        wb[(c1 + 2) * NEXP + r1] = wa1.z; wb[(c1 + 3) * NEXP + r1] = wa1.w;
    }

    const int NC = DDIM / KT;   // 256 chunks
    for (int kc = 0; kc < NC; ++kc) {
        __syncthreads();   // cur buffer ready; prev buffer's readers all done

        // prefetch next chunk into registers
        if (kc + 1 < NC) {
            const int k0 = (kc + 1) * KT;
            ha0 = *(const float4*)(hblk + (size_t)r0 * DDIM + k0 + c0);
            ha1 = *(const float4*)(hblk + (size_t)r1 * DDIM + k0 + c1);
            wa0 = *(const float4*)(W    + (size_t)r0 * DDIM + k0 + c0);
            wa1 = *(const float4*)(W    + (size_t)r1 * DDIM + k0 + c1);
        }

        // compute on current buffer
        const int cur = kc & 1;
        const float* hb = sbuf + cur * (KT * MT);
        const float* wb = sbuf + WS_OFF + cur * (KT * NEXP);
#pragma unroll
        for (int ki = 0; ki < KT; ++ki) {
            float4 hv = *(const float4*)(hb + ki * MT + tx * 4);
            ulonglong2 wv0 = *(const ulonglong2*)(wb + ki * NEXP + ty * 8);
            ulonglong2 wv1 = *(const ulonglong2*)(wb + ki * NEXP + ty * 8 + 4);
            unsigned long long h2[4];
            h2[0] = pack2(hv.x, hv.x); h2[1] = pack2(hv.y, hv.y);
            h2[2] = pack2(hv.z, hv.z); h2[3] = pack2(hv.w, hv.w);
            unsigned long long wp[4];
            wp[0] = wv0.x; wp[1] = wv0.y; wp[2] = wv1.x; wp[3] = wv1.y;
#pragma unroll
            for (int j = 0; j < 4; j++)
#pragma unroll
                for (int p = 0; p < 4; p++) fma2(acc[j][p], h2[j], wp[p]);
        }

        // store prefetched chunk into the other buffer
        if (kc + 1 < NC) {
            const int nb = (kc + 1) & 1;
            float* hn = sbuf + nb * (KT * MT);
            float* wn = sbuf + WS_OFF + nb * (KT * NEXP);
            hn[(c0 + 0) * MT + r0] = ha0.x; hn[(c0 + 1) * MT + r0] = ha0.y;
            hn[(c0 + 2) * MT + r0] = ha0.z; hn[(c0 + 3) * MT + r0] = ha0.w;
            hn[(c1 + 0) * MT + r1] = ha1.x; hn[(c1 + 1) * MT + r1] = ha1.y;
            hn[(c1 + 2) * MT + r1] = ha1.z; hn[(c1 + 3) * MT + r1] = ha1.w;
            wn[(c0 + 0) * NEXP + r0] = wa0.x; wn[(c0 + 1) * NEXP + r0] = wa0.y;
            wn[(c0 + 2) * NEXP + r0] = wa0.z; wn[(c0 + 3) * NEXP + r0] = wa0.w;
            wn[(c1 + 0) * NEXP + r1] = wa1.x; wn[(c1 + 1) * NEXP + r1] = wa1.y;
            wn[(c1 + 2) * NEXP + r1] = wa1.z; wn[(c1 + 3) * NEXP + r1] = wa1.w;
        }
    }

    // ---- epilogue: logits -> smem, then per-token softmax + top-2 ----
    __syncthreads();   // all GEMM smem reads done; safe to overwrite with logits
#pragma unroll
    for (int j = 0; j < 4; j++) {
        const int t = tx * 4 + j;
#pragma unroll
        for (int p = 0; p < 4; p++) {
            float lo, hi;
            unpack2(acc[j][p], lo, hi);
            sbuf[t * LSTRIDE + ty * 8 + p * 2 + 0] = lo;
            sbuf[t * LSTRIDE + ty * 8 + p * 2 + 1] = hi;
        }
    }
    __syncthreads();

    if (tid < MT) {
        const float* row = sbuf + tid * LSTRIDE;
        float v1 = -1e30f, v2 = -1e30f;
        int   i1 = 0,      i2 = 0;
#pragma unroll 8
        for (int e = 0; e < NEXP; ++e) {
            float l = row[e];
            if (l > v1) { v2 = v1; i2 = i1; v1 = l; i1 = e; }
            else if (l > v2) { v2 = l; i2 = e; }
        }
        float S = 0.f;
#pragma unroll 8
        for (int e = 0; e < NEXP; ++e) S += __expf(row[e] - v1);
        // gathered softmax weights g_i = exp(l_i - v1)/S ; renorm w_i = g_i/(g0+g1+EPS)
        const float e0 = 1.0f;
        const float e1 = __expf(v2 - v1);
        const float denom = e0 + e1 + 1e-9f * S;
        const float w0 = e0 / denom;
        const float w1 = e1 / denom;

        const size_t gt = (size_t)blockIdx.x * MT + tid;
        out[gt * 2 + 0] = w0;
        out[gt * 2 + 1] = w1;
        out[(size_t)2 * T_TOKENS + gt * 2 + 0] = (float)i1;
        out[(size_t)2 * T_TOKENS + gt * 2 + 1] = (float)i2;
    }
}

extern "C" void kernel_launch(void* const* d_in, const int* in_sizes, int n_in,
                              void* d_out, int out_size)
{
    const float* h = (const float*)d_in[0];
    const float* W = (const float*)d_in[1];
    float* out = (float*)d_out;
    gate_kernel<<<T_TOKENS / MT, NTHREADS>>>(h, W, out);
}